// round 16
// baseline (speedup 1.0000x reference)
#include <cuda_runtime.h>
#include <cuda_fp16.h>
#include <cstdint>

// ============================================================================
// BayesianLinear on sm_103 (base ISA — tcgen05 blocked by compute_103 target).
// fp16 single-pass GEMM (rel_err ~3e-4 < 1e-3, validated R6):
//   w = mu + softplus(rho)*eps -> fp16 (PERMUTED into mma B-fragment layout)
//   x -> fp16 (row-major, A staged via cp.async smem ring + ldsm)
//   out = x_f16 @ w_f16^T  (fp32 accum)  + bias
// R15 -> R16: BK 32->64. A-only stage is 18.4 KB so a 5-stage ring still fits
// at 2 CTAs/SM (92 KB/CTA). Halves the per-kt barrier/wait rallies (128->64)
// that dominate the remaining bubble. B path unchanged: direct LDG.64 from
// permuted global, double-buffered one 32-K half ahead.
// ============================================================================

#define IN_F   4096
#define OUT_F  4096
#define BATCH  4096

// ---------------- scratch (no cudaMalloc allowed) ----------------
__device__ __align__(16) uint32_t g_w_p[(size_t)OUT_F * IN_F / 2];  // permuted fp16x2
__device__ __align__(16) __half   g_x_h[(size_t)BATCH * IN_F];
__device__ __align__(16) float    g_bias[OUT_F];

// ---------------- helpers ----------------
__device__ __forceinline__ uint32_t smem_to_u32(const void* p) {
    uint32_t a;
    asm("{ .reg .u64 t; cvta.to.shared.u64 t, %1; cvt.u32.u64 %0, t; }" : "=r"(a) : "l"(p));
    return a;
}

__device__ __forceinline__ void cp16(uint32_t saddr, const void* gptr) {
    size_t ga = __cvta_generic_to_global(gptr);
    asm volatile("cp.async.cg.shared.global [%0], [%1], 16;"
                 :: "r"(saddr), "l"(ga) : "memory");
}
#define CP_COMMIT() asm volatile("cp.async.commit_group;" ::: "memory")
#define CP_WAIT3()  asm volatile("cp.async.wait_group 3;" ::: "memory")

__device__ __forceinline__ void ldsm_x4(uint32_t (&r)[4], uint32_t saddr) {
    asm volatile("ldmatrix.sync.aligned.m8n8.x4.shared.b16 {%0,%1,%2,%3}, [%4];"
                 : "=r"(r[0]), "=r"(r[1]), "=r"(r[2]), "=r"(r[3]) : "r"(saddr));
}

__device__ __forceinline__ uint2 ldg64(const uint32_t* p) {
    uint2 v;
    asm("ld.global.nc.v2.u32 {%0,%1}, [%2];" : "=r"(v.x), "=r"(v.y) : "l"(p));
    return v;
}

__device__ __forceinline__ void mma_f16(float (&d)[4], const uint32_t (&a)[4],
                                        uint32_t b0, uint32_t b1) {
    asm volatile(
        "mma.sync.aligned.m16n8k16.row.col.f32.f16.f16.f32 "
        "{%0,%1,%2,%3}, {%4,%5,%6,%7}, {%8,%9}, {%0,%1,%2,%3};"
        : "+f"(d[0]), "+f"(d[1]), "+f"(d[2]), "+f"(d[3])
        : "r"(a[0]), "r"(a[1]), "r"(a[2]), "r"(a[3]), "r"(b0), "r"(b1));
}

__device__ __forceinline__ uint32_t pack_h2(float a, float b) {
    __half ha = __float2half_rn(a);
    __half hb = __float2half_rn(b);
    return (uint32_t)__half_as_ushort(ha) | ((uint32_t)__half_as_ushort(hb) << 16);
}

// ============================================================================
// Pass 1 (fused): weight -> fp16 PERMUTED, x -> fp16, bias -> fp32
// ============================================================================
#define WBLK (OUT_F * (IN_F / 4) / 256)   // 16384
#define XBLK (BATCH * (IN_F / 4) / 256)   // 16384
#define BBLK (OUT_F / 256)                // 16

__global__ void __launch_bounds__(256) prep_kernel(
    const float* __restrict__ x,
    const float* __restrict__ wmu, const float* __restrict__ wrho,
    const float* __restrict__ bmu, const float* __restrict__ brho,
    const float* __restrict__ weps, const float* __restrict__ beps)
{
    int b = blockIdx.x;
    if (b < WBLK) {
        size_t i4 = (size_t)b * 256 + threadIdx.x;
        const float4 m = ((const float4*)wmu)[i4];
        const float4 r = ((const float4*)wrho)[i4];
        const float4 e = ((const float4*)weps)[i4];
        float w0 = m.x + (log1pf(expf(r.x)) + 1e-8f) * e.x;
        float w1 = m.y + (log1pf(expf(r.y)) + 1e-8f) * e.y;
        float w2 = m.z + (log1pf(expf(r.z)) + 1e-8f) * e.z;
        float w3 = m.w + (log1pf(expf(r.w)) + 1e-8f) * e.w;
        // permuted B-fragment store (m16n8k16 col-B layout):
        //   block (g=o/8, c=i0/16); lane = (o%8)*4 + ((k%8)>>1); reg = k>>3
        //   u32 slot = (g*256+c)*64 + lane*2 + reg; f16x2 = {w[k], w[k+1]}
        int o  = (int)(i4 >> 10);            // IN_F/4 = 1024 float4 per row
        int i0 = ((int)i4 & 1023) << 2;
        int g  = o >> 3, n = o & 7;
        int c  = i0 >> 4, k0 = i0 & 15;
        uint32_t base = ((uint32_t)(g * 256 + c)) << 6;   // *64 u32 per block
        uint32_t reg  = (uint32_t)(k0 >> 3);
        uint32_t l0   = (uint32_t)(n * 4 + ((k0 & 7) >> 1));
        g_w_p[base + l0 * 2 + reg]       = pack_h2(w0, w1);
        g_w_p[base + (l0 + 1) * 2 + reg] = pack_h2(w2, w3);
    } else if (b < WBLK + XBLK) {
        size_t i4 = (size_t)(b - WBLK) * 256 + threadIdx.x;
        const float4 v = ((const float4*)x)[i4];
        ((uint2*)g_x_h)[i4] = make_uint2(pack_h2(v.x, v.y), pack_h2(v.z, v.w));
    } else {
        int i = (b - WBLK - XBLK) * 256 + threadIdx.x;
        g_bias[i] = bmu[i] + (log1pf(expf(brho[i])) + 1e-8f) * beps[i];
    }
}

// ============================================================================
// Pass 2: GEMM. CTA 128x128, BK=64, 8 warps (2M x 4N, warp 64x32), 2 CTAs/SM.
// A: 5-stage cp.async smem ring + ldsm (18.4 KB/stage, A only).
// B: direct LDG.64 fragments from permuted global, double-buffered one
//    32-K half ahead (same cadence as the proven R15 stream).
// ============================================================================
#define BM 128
#define BN 128
#define BK 64
#define KPAD 72                   // fp16/row -> 144 B pitch, conflict-free ldsm
#define STAGE_BYTES (128 * 144)   // A only: 18432
#define NSTAGE 5
#define SMEM_SIZE (NSTAGE * STAGE_BYTES)   // 92160
#define NT (IN_F / BK)            // 64
#define NH (IN_F / 32)            // 128 32-K halves (B prefetch granularity)

__global__ void __launch_bounds__(256, 2) gemm_kernel(float* __restrict__ out)
{
    extern __shared__ char smem[];
    const uint32_t sbase = smem_to_u32(smem);
    const int tid  = threadIdx.x;
    const int lane = tid & 31;
    const int w    = tid >> 5;
    const int wm   = w >> 2;   // 0..1
    const int wn   = w & 3;    // 0..3
    const int m0 = blockIdx.y * BM;
    const int n0 = blockIdx.x * BN;

    float acc[4][4][4];
#pragma unroll
    for (int f = 0; f < 4; f++)
#pragma unroll
        for (int n = 0; n < 4; n++)
#pragma unroll
            for (int q = 0; q < 4; q++) acc[f][n][q] = 0.0f;

    // ---- A cp.async coords: thread t -> row t>>1 (0..127), half (t&1)
    //      4 x 16-B chunks; 128 B data per row, 16-B pitch padding untouched.
    const int lrow  = tid >> 1;
    const int lhalf = (tid & 1) << 5;                // fp16 col offset 0 or 32
    const uint32_t so = (uint32_t)(lrow * 144 + lhalf * 2);
    const size_t gx = (size_t)(m0 + lrow) * IN_F + lhalf;

    // ---- A ldmatrix fragment base (fp16 units)
    const uint32_t a_base = (uint32_t)((wm * 64 + (lane & 15)) * KPAD + (lane >> 4) * 8);

    // ---- B fragment pointer: block (g,c) at u32 offset (g*256+c)*64 + lane*2
    const uint32_t* pB = g_w_p
        + ((size_t)(n0 / 8 + wn * 4) << 14)   // g0 * 256 * 64
        + (uint32_t)(lane * 2);

#define LOAD_STAGE(ST, KT) do {                                    \
    uint32_t sb_ = sbase + (uint32_t)(ST) * STAGE_BYTES;           \
    size_t ko_ = (size_t)(KT) * BK;                                \
    const __half* gx_ = g_x_h + gx + ko_;                          \
    cp16(sb_ + so,      gx_);                                      \
    cp16(sb_ + so + 16, gx_ + 8);                                  \
    cp16(sb_ + so + 32, gx_ + 16);                                 \
    cp16(sb_ + so + 48, gx_ + 24);                                 \
} while (0)

// Load B fragments for 32-K half KH (two k16 blocks c = KH*2 + {0,1})
#define LDG_B(DST, KH) do {                                        \
    uint32_t cbase_ = (uint32_t)(KH) * 2;                          \
    _Pragma("unroll")                                              \
    for (int ks_ = 0; ks_ < 2; ks_++)                              \
        _Pragma("unroll")                                          \
        for (int j_ = 0; j_ < 4; j_++)                             \
            (DST)[ks_][j_] = ldg64(pB + (size_t)j_ * 16384 +       \
                                   (size_t)(cbase_ + ks_) * 64);   \
} while (0)

    LOAD_STAGE(0, 0); CP_COMMIT();
    LOAD_STAGE(1, 1); CP_COMMIT();
    LOAD_STAGE(2, 2); CP_COMMIT();
    LOAD_STAGE(3, 3); CP_COMMIT();

    uint2 Bb[2][2][4];             // [half parity][k16 within half][j]
    LDG_B(Bb[0], 0);

    int st = 0;
#pragma unroll 1
    for (int kt = 0; kt < NT; kt++) {
        CP_WAIT3();            // <=3 groups pending -> stage kt complete
        __syncthreads();       // publish stage kt; stage (kt-1)%5 readers done

        if (kt + 4 < NT) {
            int st4 = st + 4; if (st4 >= NSTAGE) st4 -= NSTAGE;
            LOAD_STAGE(st4, kt + 4);
        }
        CP_COMMIT();           // fixed group accounting

        const uint32_t sb = sbase + (uint32_t)st * STAGE_BYTES;
        st++; if (st == NSTAGE) st = 0;

#pragma unroll
        for (int h = 0; h < 2; h++) {
            const int kh  = kt * 2 + h;
            const int cur = kh & 1;
            // prefetch B for the next 32-K half (L2-resident, ~1000 cyc ahead)
            if (kh + 1 < NH) LDG_B(Bb[cur ^ 1], kh + 1);

#pragma unroll
            for (int ks2 = 0; ks2 < 2; ks2++) {
                const int ks = h * 2 + ks2;
#pragma unroll
                for (int f = 0; f < 4; f++) {
                    uint32_t a[4];
                    ldsm_x4(a, sb + (a_base + (uint32_t)(f * 16 * KPAD + ks * 16)) * 2);
#pragma unroll
                    for (int n = 0; n < 4; n++)
                        mma_f16(acc[f][n], a, Bb[cur][ks2][n].x, Bb[cur][ks2][n].y);
                }
            }
        }
    }

    // ---- epilogue: add bias, write out ----
#pragma unroll
    for (int n = 0; n < 4; n++) {
        const int c = n0 + wn * 32 + n * 8 + (lane & 3) * 2;
        const float2 bs = *(const float2*)(g_bias + c);
#pragma unroll
        for (int f = 0; f < 4; f++) {
            const int r = m0 + wm * 64 + f * 16 + (lane >> 2);
            float2 v0, v1;
            v0.x = acc[f][n][0] + bs.x; v0.y = acc[f][n][1] + bs.y;
            v1.x = acc[f][n][2] + bs.x; v1.y = acc[f][n][3] + bs.y;
            *(float2*)(out + (size_t)r * OUT_F + c) = v0;
            *(float2*)(out + (size_t)(r + 8) * OUT_F + c) = v1;
        }
    }
}

// ============================================================================
// launch
// ============================================================================
extern "C" void kernel_launch(void* const* d_in, const int* in_sizes, int n_in,
                              void* d_out, int out_size)
{
    const float* x    = (const float*)d_in[0];
    const float* wmu  = (const float*)d_in[1];
    const float* wrho = (const float*)d_in[2];
    const float* bmu  = (const float*)d_in[3];
    const float* brho = (const float*)d_in[4];
    const float* weps = (const float*)d_in[5];
    const float* beps = (const float*)d_in[6];
    float* out = (float*)d_out;

    prep_kernel<<<WBLK + XBLK + BBLK, 256>>>(x, wmu, wrho, bmu, brho, weps, beps);

    static bool attr_set = false;
    if (!attr_set) {
        cudaFuncSetAttribute(gemm_kernel, cudaFuncAttributeMaxDynamicSharedMemorySize, SMEM_SIZE);
        attr_set = true;
    }
    dim3 grid(OUT_F / BN, BATCH / BM);
    gemm_kernel<<<grid, 256, SMEM_SIZE>>>(out);
}

// round 17
// speedup vs baseline: 1.2226x; 1.2226x over previous
#include <cuda_runtime.h>
#include <cuda_fp16.h>
#include <cstdint>

// ============================================================================
// BayesianLinear on sm_103 (base ISA — tcgen05 blocked by compute_103 target).
// fp16 single-pass GEMM (rel_err ~3e-4 < 1e-3, validated R6):
//   w = mu + softplus(rho)*eps -> fp16 (PERMUTED into mma B-fragment layout)
//   x -> fp16 (row-major, A staged via cp.async smem ring + ldsm)
//   out = x_f16 @ w_f16^T  (fp32 accum)  + bias
// R16 -> R17: revert to champion R15 (BK=32, 5-stage ring, B direct-LDG) and
// split each CTA into TWO independent barrier domains: warp-quad wm loads and
// reads only A rows [wm*64, wm*64+64), synced by named bar.sync (ids 1,2)
// instead of __syncthreads. 4 staggered sync domains per SM interleave the
// post-barrier crossbar bursts with other domains' MMA streams.
// Prep: series log1p for the small-argument range (guarded fallback).
// ============================================================================

#define IN_F   4096
#define OUT_F  4096
#define BATCH  4096

// ---------------- scratch (no cudaMalloc allowed) ----------------
__device__ __align__(16) uint32_t g_w_p[(size_t)OUT_F * IN_F / 2];  // permuted fp16x2
__device__ __align__(16) __half   g_x_h[(size_t)BATCH * IN_F];
__device__ __align__(16) float    g_bias[OUT_F];

// ---------------- helpers ----------------
__device__ __forceinline__ uint32_t smem_to_u32(const void* p) {
    uint32_t a;
    asm("{ .reg .u64 t; cvta.to.shared.u64 t, %1; cvt.u32.u64 %0, t; }" : "=r"(a) : "l"(p));
    return a;
}

__device__ __forceinline__ void cp16(uint32_t saddr, const void* gptr) {
    size_t ga = __cvta_generic_to_global(gptr);
    asm volatile("cp.async.cg.shared.global [%0], [%1], 16;"
                 :: "r"(saddr), "l"(ga) : "memory");
}
#define CP_COMMIT() asm volatile("cp.async.commit_group;" ::: "memory")
#define CP_WAIT3()  asm volatile("cp.async.wait_group 3;" ::: "memory")

// named barrier over 128 threads (ids 1 and 2)
#define HALF_BAR(ID) asm volatile("bar.sync %0, 128;" :: "r"(ID) : "memory")

__device__ __forceinline__ void ldsm_x4(uint32_t (&r)[4], uint32_t saddr) {
    asm volatile("ldmatrix.sync.aligned.m8n8.x4.shared.b16 {%0,%1,%2,%3}, [%4];"
                 : "=r"(r[0]), "=r"(r[1]), "=r"(r[2]), "=r"(r[3]) : "r"(saddr));
}

__device__ __forceinline__ uint2 ldg64(const uint32_t* p) {
    uint2 v;
    asm("ld.global.nc.v2.u32 {%0,%1}, [%2];" : "=r"(v.x), "=r"(v.y) : "l"(p));
    return v;
}

__device__ __forceinline__ void mma_f16(float (&d)[4], const uint32_t (&a)[4],
                                        uint32_t b0, uint32_t b1) {
    asm volatile(
        "mma.sync.aligned.m16n8k16.row.col.f32.f16.f16.f32 "
        "{%0,%1,%2,%3}, {%4,%5,%6,%7}, {%8,%9}, {%0,%1,%2,%3};"
        : "+f"(d[0]), "+f"(d[1]), "+f"(d[2]), "+f"(d[3])
        : "r"(a[0]), "r"(a[1]), "r"(a[2]), "r"(a[3]), "r"(b0), "r"(b1));
}

__device__ __forceinline__ uint32_t pack_h2(float a, float b) {
    __half ha = __float2half_rn(a);
    __half hb = __float2half_rn(b);
    return (uint32_t)__half_as_ushort(ha) | ((uint32_t)__half_as_ushort(hb) << 16);
}

// softplus(r) = log1p(exp(r)); for t=exp(r) < 0.125 use 4-term series
// (abs err < 7e-6, rel err vs sigma < 5e-5 — far under fp16 quantization)
__device__ __forceinline__ float softplus_f(float r) {
    float t = expf(r);
    float series = t * (1.0f + t * (-0.5f + t * (0.33333333f + t * (-0.25f))));
    return (t < 0.125f) ? series : log1pf(t);
}

// ============================================================================
// Pass 1 (fused): weight -> fp16 PERMUTED, x -> fp16, bias -> fp32
// ============================================================================
#define WBLK (OUT_F * (IN_F / 4) / 256)   // 16384
#define XBLK (BATCH * (IN_F / 4) / 256)   // 16384
#define BBLK (OUT_F / 256)                // 16

__global__ void __launch_bounds__(256) prep_kernel(
    const float* __restrict__ x,
    const float* __restrict__ wmu, const float* __restrict__ wrho,
    const float* __restrict__ bmu, const float* __restrict__ brho,
    const float* __restrict__ weps, const float* __restrict__ beps)
{
    int b = blockIdx.x;
    if (b < WBLK) {
        size_t i4 = (size_t)b * 256 + threadIdx.x;
        const float4 m = ((const float4*)wmu)[i4];
        const float4 r = ((const float4*)wrho)[i4];
        const float4 e = ((const float4*)weps)[i4];
        float w0 = m.x + (softplus_f(r.x) + 1e-8f) * e.x;
        float w1 = m.y + (softplus_f(r.y) + 1e-8f) * e.y;
        float w2 = m.z + (softplus_f(r.z) + 1e-8f) * e.z;
        float w3 = m.w + (softplus_f(r.w) + 1e-8f) * e.w;
        // permuted B-fragment store (m16n8k16 col-B layout):
        //   block (g=o/8, c=i0/16); lane = (o%8)*4 + ((k%8)>>1); reg = k>>3
        //   u32 slot = (g*256+c)*64 + lane*2 + reg; f16x2 = {w[k], w[k+1]}
        int o  = (int)(i4 >> 10);            // IN_F/4 = 1024 float4 per row
        int i0 = ((int)i4 & 1023) << 2;
        int g  = o >> 3, n = o & 7;
        int c  = i0 >> 4, k0 = i0 & 15;
        uint32_t base = ((uint32_t)(g * 256 + c)) << 6;   // *64 u32 per block
        uint32_t reg  = (uint32_t)(k0 >> 3);
        uint32_t l0   = (uint32_t)(n * 4 + ((k0 & 7) >> 1));
        g_w_p[base + l0 * 2 + reg]       = pack_h2(w0, w1);
        g_w_p[base + (l0 + 1) * 2 + reg] = pack_h2(w2, w3);
    } else if (b < WBLK + XBLK) {
        size_t i4 = (size_t)(b - WBLK) * 256 + threadIdx.x;
        const float4 v = ((const float4*)x)[i4];
        ((uint2*)g_x_h)[i4] = make_uint2(pack_h2(v.x, v.y), pack_h2(v.z, v.w));
    } else {
        int i = (b - WBLK - XBLK) * 256 + threadIdx.x;
        g_bias[i] = bmu[i] + (softplus_f(brho[i]) + 1e-8f) * beps[i];
    }
}

// ============================================================================
// Pass 2: GEMM. CTA 128x128, BK=32, 8 warps (2M x 4N, warp 64x32), 2 CTAs/SM.
// A: 5-stage cp.async smem ring + ldsm, SPLIT into two independent 64-row
//    halves (threads 0-127 own rows 0-63, threads 128-255 own rows 64-127),
//    each synced by its own named barrier -> 4 sync domains per SM.
// B: direct LDG.64 fragments from permuted global, double-buffered 1 kt ahead.
// ============================================================================
#define BM 128
#define BN 128
#define BK 32
#define KPAD 40                   // fp16/row -> 80 B pitch, conflict-free ldsm
#define STAGE_BYTES (128 * 80)    // A only: 10240 (rows 0-63 half0, 64-127 half1)
#define NSTAGE 5
#define SMEM_SIZE (NSTAGE * STAGE_BYTES)   // 51200
#define NT (IN_F / BK)            // 128

__global__ void __launch_bounds__(256, 2) gemm_kernel(float* __restrict__ out)
{
    extern __shared__ char smem[];
    const uint32_t sbase = smem_to_u32(smem);
    const int tid  = threadIdx.x;
    const int lane = tid & 31;
    const int w    = tid >> 5;
    const int wm   = w >> 2;   // 0..1  (== tid>>7: warps 0-3 are threads 0-127)
    const int wn   = w & 3;    // 0..3
    const int m0 = blockIdx.y * BM;
    const int n0 = blockIdx.x * BN;
    const int bar_id = wm + 1;             // named barrier 1 or 2

    float acc[4][4][4];
#pragma unroll
    for (int f = 0; f < 4; f++)
#pragma unroll
        for (int n = 0; n < 4; n++)
#pragma unroll
            for (int q = 0; q < 4; q++) acc[f][n][q] = 0.0f;

    // ---- A cp.async coords: each 128-thread half loads its own 64 rows.
    // half h thread ht (0..127): row = h*64 + (ht>>1), 32 B = 2 chunks at
    // byte offset (ht&1)*32 within the 64-B data region of the row.
    const int ht   = tid & 127;
    const int lrow = wm * 64 + (ht >> 1);
    const int lc8  = (ht & 1) << 4;                  // fp16 col offset 0 or 16
    const uint32_t lso = (uint32_t)(lrow * 80 + lc8 * 2);
    const size_t gx = (size_t)(m0 + lrow) * IN_F + lc8;

    // ---- A ldmatrix fragment base (fp16 units) — within own half's rows
    const uint32_t a_base = (uint32_t)((wm * 64 + (lane & 15)) * KPAD + (lane >> 4) * 8);

    // ---- B fragment pointer: block (g,c) at u32 offset (g*256+c)*64 + lane*2
    const uint32_t* pB = g_w_p
        + ((size_t)(n0 / 8 + wn * 4) << 14)   // g0 * 256 * 64
        + (uint32_t)(lane * 2);

#define LOAD_STAGE(ST, KT) do {                                    \
    uint32_t sb_ = sbase + (uint32_t)(ST) * STAGE_BYTES;           \
    size_t ko_ = (size_t)(KT) * BK;                                \
    const __half* gx_ = g_x_h + gx + ko_;                          \
    cp16(sb_ + lso,      gx_);                                     \
    cp16(sb_ + lso + 16, gx_ + 8);                                 \
} while (0)

#define LDG_B(DST, KT) do {                                        \
    uint32_t cbase_ = (uint32_t)(KT) * 2;                          \
    _Pragma("unroll")                                              \
    for (int ks_ = 0; ks_ < 2; ks_++)                              \
        _Pragma("unroll")                                          \
        for (int j_ = 0; j_ < 4; j_++)                             \
            (DST)[ks_][j_] = ldg64(pB + (size_t)j_ * 16384 +       \
                                   (size_t)(cbase_ + ks_) * 64);   \
} while (0)

    LOAD_STAGE(0, 0); CP_COMMIT();
    LOAD_STAGE(1, 1); CP_COMMIT();
    LOAD_STAGE(2, 2); CP_COMMIT();
    LOAD_STAGE(3, 3); CP_COMMIT();

    uint2 Bb[2][2][4];             // [parity][ks][j]
    LDG_B(Bb[0], 0);

    int st = 0;
#pragma unroll 2
    for (int kt = 0; kt < NT; kt++) {
        const int cur = kt & 1, nxt = cur ^ 1;

        // prefetch B for kt+1 (independent of smem/barriers; L2-resident)
        if (kt + 1 < NT) LDG_B(Bb[nxt], kt + 1);

        CP_WAIT3();            // own groups: stage kt complete (this thread)
        HALF_BAR(bar_id);      // publish own half of stage kt; own half of
                               // stage (kt-1)%5 has no remaining readers

        if (kt + 4 < NT) {
            int st4 = st + 4; if (st4 >= NSTAGE) st4 -= NSTAGE;
            LOAD_STAGE(st4, kt + 4);
        }
        CP_COMMIT();           // fixed group accounting

        const uint32_t sb = sbase + (uint32_t)st * STAGE_BYTES;
        st++; if (st == NSTAGE) st = 0;

#pragma unroll
        for (int ks = 0; ks < 2; ks++) {
#pragma unroll
            for (int f = 0; f < 4; f++) {
                uint32_t a[4];
                ldsm_x4(a, sb + (a_base + (uint32_t)(f * 16 * KPAD + ks * 16)) * 2);
#pragma unroll
                for (int n = 0; n < 4; n++)
                    mma_f16(acc[f][n], a, Bb[cur][ks][n].x, Bb[cur][ks][n].y);
            }
        }
    }

    // ---- epilogue: add bias, write out ----
#pragma unroll
    for (int n = 0; n < 4; n++) {
        const int c = n0 + wn * 32 + n * 8 + (lane & 3) * 2;
        const float2 bs = *(const float2*)(g_bias + c);
#pragma unroll
        for (int f = 0; f < 4; f++) {
            const int r = m0 + wm * 64 + f * 16 + (lane >> 2);
            float2 v0, v1;
            v0.x = acc[f][n][0] + bs.x; v0.y = acc[f][n][1] + bs.y;
            v1.x = acc[f][n][2] + bs.x; v1.y = acc[f][n][3] + bs.y;
            *(float2*)(out + (size_t)r * OUT_F + c) = v0;
            *(float2*)(out + (size_t)(r + 8) * OUT_F + c) = v1;
        }
    }
}

// ============================================================================
// launch
// ============================================================================
extern "C" void kernel_launch(void* const* d_in, const int* in_sizes, int n_in,
                              void* d_out, int out_size)
{
    const float* x    = (const float*)d_in[0];
    const float* wmu  = (const float*)d_in[1];
    const float* wrho = (const float*)d_in[2];
    const float* bmu  = (const float*)d_in[3];
    const float* brho = (const float*)d_in[4];
    const float* weps = (const float*)d_in[5];
    const float* beps = (const float*)d_in[6];
    float* out = (float*)d_out;

    prep_kernel<<<WBLK + XBLK + BBLK, 256>>>(x, wmu, wrho, bmu, brho, weps, beps);

    static bool attr_set = false;
    if (!attr_set) {
        cudaFuncSetAttribute(gemm_kernel, cudaFuncAttributeMaxDynamicSharedMemorySize, SMEM_SIZE);
        attr_set = true;
    }
    dim3 grid(OUT_F / BN, BATCH / BM);
    gemm_kernel<<<grid, 256, SMEM_SIZE>>>(out);
}